// round 6
// baseline (speedup 1.0000x reference)
#include <cuda_runtime.h>
#include <mma.h>
using namespace nvcuda;

#define NN 50000
#define NPAD 50048     // NN rounded up to 128 (GEMM tile)
#define EE 800000
#define TT (EE + NN)
#define HH 4
#define CHN 256        // H * C (both layers)
#define C2  64

// ---------------- scratch (device globals; no allocation allowed) ----------
__device__ __align__(16) float g_h[(size_t)NPAD * CHN];   // GEMM output
__device__ __align__(16) float g_x1[(size_t)NPAD * CHN];  // relu(layer1 out)
__device__ __align__(16) float g_as[NN * HH];
__device__ __align__(16) float g_ad[NN * HH];
__device__ __align__(16) float g_e[(size_t)TT * HH];      // CSR-ordered logits
__device__ int   g_deg[NN];
__device__ int   g_rowptr[NN + 1];
__device__ int   g_cursor[NN];
__device__ int   g_srcs[TT];                // CSR (by dst): source node
__device__ int   g_dsts[TT];                // CSR: destination node

// ---------------- CSR build -------------------------------------------------
__global__ void k_zero_deg() {
    int i = blockIdx.x * blockDim.x + threadIdx.x;
    if (i < NN) g_deg[i] = 0;
}

__global__ void k_hist(const int* __restrict__ ei) {
    int t = blockIdx.x * blockDim.x + threadIdx.x;
    if (t >= TT) return;
    int d = (t < EE) ? ei[EE + t] : (t - EE);
    atomicAdd(&g_deg[d], 1);
}

__global__ void k_scan() {
    __shared__ int s[1024];
    const int tid = threadIdx.x;
    const int CHK = (NN + 1023) / 1024;
    int start = tid * CHK;
    int end   = min(start + CHK, NN);
    int sum = 0;
    for (int i = start; i < end; i++) sum += g_deg[i];
    s[tid] = sum;
    __syncthreads();
    for (int off = 1; off < 1024; off <<= 1) {
        int v = (tid >= off) ? s[tid - off] : 0;
        __syncthreads();
        s[tid] += v;
        __syncthreads();
    }
    int run = s[tid] - sum;   // exclusive prefix for this chunk
    for (int i = start; i < end; i++) {
        g_rowptr[i] = run;
        g_cursor[i] = run;
        run += g_deg[i];
    }
    if (tid == 1023) g_rowptr[NN] = s[1023];
}

__global__ void k_scatter(const int* __restrict__ ei) {
    int t = blockIdx.x * blockDim.x + threadIdx.x;
    if (t >= TT) return;
    int sv, dv;
    if (t < EE) { sv = ei[t]; dv = ei[EE + t]; }
    else        { sv = dv = t - EE; }
    int pos = atomicAdd(&g_cursor[dv], 1);
    g_srcs[pos] = sv;
    g_dsts[pos] = dv;
}

// ---------------- tf32 tensor-core GEMM: C[M,256] = A[M,K] @ B[K,256] -------
// BM=128, BN=128, BK=16; double-buffered smem; tf32 pre-converted at fill.
// 8 warps in 4x2; warp tile 32x64 via 2x4 m16n16k8 frags.
#define BM 128
#define BN 128
#define BK 16
#define LDA (BK + 4)    // 20 floats = 80B (mult of 16B)
#define LDB (BN + 4)    // 132 floats = 528B (mult of 16B)

__global__ void __launch_bounds__(256) k_gemm(const float* __restrict__ Aext,
                                              const float* __restrict__ B,
                                              int M, int K, int layer) {
    const float* __restrict__ A = (layer == 1) ? Aext : (const float*)g_x1;

    __shared__ __align__(16) float As[2][BM][LDA];   // 2*10240 B
    __shared__ __align__(16) float Bs[2][BK][LDB];   // 2*8448  B

    const int tid = threadIdx.x;
    const int wid = tid >> 5;
    const int wm = wid >> 1;      // 0..3  -> rows wm*32
    const int wn = wid & 1;       // 0..1  -> cols wn*64
    const int m0 = blockIdx.y * BM;
    const int n0 = blockIdx.x * BN;

    // A tile: 128x16 = 512 float4 -> 2 per thread
    const int arow[2] = { (tid + 0) >> 2, (tid + 256) >> 2 };
    const int acol = (tid & 3) * 4;
    // B tile: 16x128 = 512 float4 -> 2 per thread
    const int brow[2] = { (tid + 0) >> 5, (tid + 256) >> 5 };
    const int bcol = (tid & 31) * 4;

    float4 ra[2], rb[2];

    auto loadG = [&](int k0) {
#pragma unroll
        for (int i = 0; i < 2; i++) {
            float4 v = make_float4(0.f, 0.f, 0.f, 0.f);
            if (m0 + arow[i] < M)
                v = *(const float4*)&A[(size_t)(m0 + arow[i]) * K + k0 + acol];
            ra[i] = v;
        }
#pragma unroll
        for (int i = 0; i < 2; i++)
            rb[i] = *(const float4*)&B[(size_t)(k0 + brow[i]) * CHN + n0 + bcol];
    };
    auto storeS = [&](int buf) {
#pragma unroll
        for (int i = 0; i < 2; i++) {
            float* p = &As[buf][arow[i]][acol];
            p[0] = wmma::__float_to_tf32(ra[i].x);
            p[1] = wmma::__float_to_tf32(ra[i].y);
            p[2] = wmma::__float_to_tf32(ra[i].z);
            p[3] = wmma::__float_to_tf32(ra[i].w);
        }
#pragma unroll
        for (int i = 0; i < 2; i++) {
            float* p = &Bs[buf][brow[i]][bcol];
            p[0] = wmma::__float_to_tf32(rb[i].x);
            p[1] = wmma::__float_to_tf32(rb[i].y);
            p[2] = wmma::__float_to_tf32(rb[i].z);
            p[3] = wmma::__float_to_tf32(rb[i].w);
        }
    };

    wmma::fragment<wmma::accumulator, 16, 16, 8, float> c[2][4];
#pragma unroll
    for (int i = 0; i < 2; i++)
#pragma unroll
        for (int j = 0; j < 4; j++) wmma::fill_fragment(c[i][j], 0.f);

    loadG(0);
    storeS(0);
    __syncthreads();

    int buf = 0;
    for (int k0 = 0; k0 < K; k0 += BK) {
        const bool has_next = (k0 + BK) < K;
        if (has_next) loadG(k0 + BK);   // prefetch into registers

#pragma unroll
        for (int kk = 0; kk < BK; kk += 8) {
            wmma::fragment<wmma::matrix_a, 16, 16, 8, wmma::precision::tf32, wmma::row_major> a[2];
            wmma::fragment<wmma::matrix_b, 16, 16, 8, wmma::precision::tf32, wmma::row_major> b[4];
#pragma unroll
            for (int i = 0; i < 2; i++)
                wmma::load_matrix_sync(a[i], &As[buf][wm * 32 + i * 16][kk], LDA);
#pragma unroll
            for (int j = 0; j < 4; j++)
                wmma::load_matrix_sync(b[j], &Bs[buf][kk][wn * 64 + j * 16], LDB);
#pragma unroll
            for (int i = 0; i < 2; i++)
#pragma unroll
                for (int j = 0; j < 4; j++)
                    wmma::mma_sync(c[i][j], a[i], b[j], c[i][j]);
        }

        if (has_next) {
            storeS(buf ^ 1);
            __syncthreads();
            buf ^= 1;
        }
    }

    // store (g_h padded to NPAD rows, so unguarded store is safe)
#pragma unroll
    for (int i = 0; i < 2; i++)
#pragma unroll
        for (int j = 0; j < 4; j++)
            wmma::store_matrix_sync(
                &g_h[(size_t)(m0 + wm * 32 + i * 16) * CHN + n0 + wn * 64 + j * 16],
                c[i][j], CHN, wmma::mem_row_major);
}

// ---------------- alpha_src / alpha_dst per (node, head) --------------------
__global__ void k_alpha(const float* __restrict__ att_s,
                        const float* __restrict__ att_d) {
    int w = (blockIdx.x * blockDim.x + threadIdx.x) >> 5;
    int lane = threadIdx.x & 31;
    if (w >= NN * HH) return;
    int n = w >> 2, hh = w & 3;
    const float* row = g_h + (size_t)n * CHN + hh * 64;
    float v1 = row[lane], v2 = row[lane + 32];
    float s = v1 * att_s[hh * 64 + lane] + v2 * att_s[hh * 64 + lane + 32];
    float d = v1 * att_d[hh * 64 + lane] + v2 * att_d[hh * 64 + lane + 32];
#pragma unroll
    for (int o = 16; o; o >>= 1) {
        s += __shfl_xor_sync(0xffffffffu, s, o);
        d += __shfl_xor_sync(0xffffffffu, d, o);
    }
    if (lane == 0) { g_as[w] = s; g_ad[w] = d; }
}

// ---------------- per-edge logits, CSR order ---------------------------------
__device__ __forceinline__ float lrelu(float v) { return v > 0.f ? v : 0.2f * v; }

__global__ void k_edge() {
    int p = blockIdx.x * blockDim.x + threadIdx.x;
    if (p >= TT) return;
    int sv = g_srcs[p], dv = g_dsts[p];
    float4 as = *(const float4*)&g_as[sv * 4];
    float4 ad = *(const float4*)&g_ad[dv * 4];
    float4 e;
    e.x = lrelu(as.x + ad.x);
    e.y = lrelu(as.y + ad.y);
    e.z = lrelu(as.z + ad.z);
    e.w = lrelu(as.w + ad.w);
    *(float4*)&g_e[(size_t)p * 4] = e;
}

// ---------------- per-node softmax + aggregation (block per node) -----------
// 4 edge-slots x 64 threads x float4 channels; final 4-way smem reduce.
template <int LAYER>
__global__ void __launch_bounds__(256) k_agg(const float* __restrict__ bias,
                                             float* __restrict__ outext) {
    const int n = blockIdx.x;
    const int tid = threadIdx.x;
    __shared__ float sh_m[4], sh_inv[4];
    __shared__ float s_alpha[64 * 4];
    __shared__ int s_src[64];
    __shared__ __align__(16) float s_red[256 * 4];

    const int row = g_rowptr[n];
    const int deg = g_rowptr[n + 1] - row;
    const int wid = tid >> 5, lane = tid & 31;

    if (wid < 4) {
        float m = -1e30f;
        for (int j = lane; j < deg; j += 32)
            m = fmaxf(m, g_e[(size_t)(row + j) * 4 + wid]);
#pragma unroll
        for (int o = 16; o; o >>= 1) m = fmaxf(m, __shfl_xor_sync(0xffffffffu, m, o));
        float s = 0.f;
        for (int j = lane; j < deg; j += 32)
            s += __expf(g_e[(size_t)(row + j) * 4 + wid] - m);
#pragma unroll
        for (int o = 16; o; o >>= 1) s += __shfl_xor_sync(0xffffffffu, s, o);
        if (lane == 0) { sh_m[wid] = m; sh_inv[wid] = 1.f / (s + 1e-16f); }
    }
    __syncthreads();

    const int grp = tid >> 6;        // edge slot 0..3
    const int ch4 = tid & 63;        // float4 channel group -> channels ch4*4..+3
    const int head = ch4 >> 4;
    float4 acc = make_float4(0.f, 0.f, 0.f, 0.f);

    for (int c0 = 0; c0 < deg; c0 += 64) {
        int cn = min(64, deg - c0);
        if (tid < cn * 4) {
            int j = tid >> 2, hh = tid & 3;
            s_alpha[tid] = __expf(g_e[(size_t)(row + c0 + j) * 4 + hh] - sh_m[hh]) * sh_inv[hh];
        }
        if (tid < cn) s_src[tid] = g_srcs[row + c0 + tid];
        __syncthreads();
        for (int j = grp; j < cn; j += 4) {
            float a = s_alpha[j * 4 + head];
            const float4 hv = *(const float4*)&g_h[(size_t)s_src[j] * CHN + ch4 * 4];
            acc.x += a * hv.x;
            acc.y += a * hv.y;
            acc.z += a * hv.z;
            acc.w += a * hv.w;
        }
        __syncthreads();
    }

    // cross-slot reduce
    *(float4*)&s_red[tid * 4] = acc;
    __syncthreads();
    if (grp == 0) {
        float4 r = acc;
#pragma unroll
        for (int g2 = 1; g2 < 4; g2++) {
            const float4 o = *(const float4*)&s_red[(g2 * 64 + ch4) * 4];
            r.x += o.x; r.y += o.y; r.z += o.z; r.w += o.w;
        }
        const int c = ch4 * 4;
        if (LAYER == 1) {
            const float4 b = *(const float4*)&bias[c];
            float4 o;
            o.x = fmaxf(r.x + b.x, 0.f);
            o.y = fmaxf(r.y + b.y, 0.f);
            o.z = fmaxf(r.z + b.z, 0.f);
            o.w = fmaxf(r.w + b.w, 0.f);
            *(float4*)&g_x1[(size_t)n * CHN + c] = o;
        } else {
            *(float4*)&s_red[c] = r;   // s_red[ch] = total[ch]
        }
    }
    if (LAYER == 2) {
        __syncthreads();
        if (tid < 64)
            outext[(size_t)n * C2 + tid] =
                0.25f * (s_red[tid] + s_red[64 + tid] + s_red[128 + tid] + s_red[192 + tid]) +
                bias[tid];
    }
}

// ---------------- launch -----------------------------------------------------
extern "C" void kernel_launch(void* const* d_in, const int* in_sizes, int n_in,
                              void* d_out, int out_size) {
    const float* x   = (const float*)d_in[0];
    const int*   ei  = (const int*)d_in[1];
    const float* W1  = (const float*)d_in[2];
    const float* as1 = (const float*)d_in[3];
    const float* ad1 = (const float*)d_in[4];
    const float* b1  = (const float*)d_in[5];
    const float* W2  = (const float*)d_in[6];
    const float* as2 = (const float*)d_in[7];
    const float* ad2 = (const float*)d_in[8];
    const float* b2  = (const float*)d_in[9];
    float* out = (float*)d_out;

    // CSR build (shared by both layers)
    k_zero_deg<<<(NN + 255) / 256, 256>>>();
    k_hist<<<(TT + 255) / 256, 256>>>(ei);
    k_scan<<<1, 1024>>>();
    k_scatter<<<(TT + 255) / 256, 256>>>(ei);

    dim3 gemm_grid(CHN / BN, NPAD / BM);
    int alpha_blocks = (NN * HH * 32 + 255) / 256;

    // ----- layer 1 -----
    k_gemm<<<gemm_grid, 256>>>(x, W1, NN, 128, 1);
    k_alpha<<<alpha_blocks, 256>>>(as1, ad1);
    k_edge<<<(TT + 255) / 256, 256>>>();
    k_agg<1><<<NN, 256>>>(b1, nullptr);

    // ----- layer 2 -----
    k_gemm<<<gemm_grid, 256>>>(nullptr, W2, NN, 256, 2);
    k_alpha<<<alpha_blocks, 256>>>(as2, ad2);
    k_edge<<<(TT + 255) / 256, 256>>>();
    k_agg<2><<<NN, 256>>>(b2, out);
}

// round 7
// speedup vs baseline: 1.1119x; 1.1119x over previous
#include <cuda_runtime.h>
#include <mma.h>
using namespace nvcuda;

#define NN 50000
#define NPAD 50048     // NN rounded up to 128 (GEMM tile)
#define EE 800000
#define TT (EE + NN)
#define HH 4
#define CHN 256        // H * C (both layers)
#define C2  64

// ---------------- scratch (device globals; no allocation allowed) ----------
__device__ __align__(16) float g_h[(size_t)NPAD * CHN];   // GEMM output
__device__ __align__(16) float g_x1[(size_t)NPAD * CHN];  // relu(layer1 out)
__device__ __align__(16) float g_as[NN * HH];
__device__ __align__(16) float g_ad[NN * HH];
__device__ __align__(16) float g_e[(size_t)TT * HH];      // CSR-ordered logits
__device__ int   g_deg[NN];
__device__ int   g_rowptr[NN + 1];
__device__ int   g_cursor[NN];
__device__ int   g_srcs[TT];                // CSR (by dst): source node
__device__ int   g_dsts[TT];                // CSR: destination node

// ---------------- CSR build -------------------------------------------------
__global__ void k_zero_deg() {
    int i = blockIdx.x * blockDim.x + threadIdx.x;
    if (i < NN) g_deg[i] = 0;
}

__global__ void k_hist(const int* __restrict__ ei) {
    int t = blockIdx.x * blockDim.x + threadIdx.x;
    if (t >= TT) return;
    int d = (t < EE) ? ei[EE + t] : (t - EE);
    atomicAdd(&g_deg[d], 1);
}

__global__ void k_scan() {
    __shared__ int s[1024];
    const int tid = threadIdx.x;
    const int CHK = (NN + 1023) / 1024;
    int start = tid * CHK;
    int end   = min(start + CHK, NN);
    int sum = 0;
    for (int i = start; i < end; i++) sum += g_deg[i];
    s[tid] = sum;
    __syncthreads();
    for (int off = 1; off < 1024; off <<= 1) {
        int v = (tid >= off) ? s[tid - off] : 0;
        __syncthreads();
        s[tid] += v;
        __syncthreads();
    }
    int run = s[tid] - sum;   // exclusive prefix for this chunk
    for (int i = start; i < end; i++) {
        g_rowptr[i] = run;
        g_cursor[i] = run;
        run += g_deg[i];
    }
    if (tid == 1023) g_rowptr[NN] = s[1023];
}

__global__ void k_scatter(const int* __restrict__ ei) {
    int t = blockIdx.x * blockDim.x + threadIdx.x;
    if (t >= TT) return;
    int sv, dv;
    if (t < EE) { sv = ei[t]; dv = ei[EE + t]; }
    else        { sv = dv = t - EE; }
    int pos = atomicAdd(&g_cursor[dv], 1);
    g_srcs[pos] = sv;
    g_dsts[pos] = dv;
}

// ---------------- tf32 tensor-core GEMM + fused alpha epilogue --------------
// C[M,256] = A[M,K] @ B[K,256]. BM=128, BN=64, BK=32; double-buffered dynamic
// smem (54.3KB); tf32 pre-converted at fill; 8 warps 4x2; warp tile 32x32.
// Epilogue: block covers exactly one head (BN=64=C) -> computes alpha_s/alpha_d
// for its 128 rows from smem-staged accumulators.
#define BM 128
#define BN 64
#define BK 32
#define LDA (BK + 4)   // 36 floats
#define LDB (BN + 4)   // 68 floats
#define ASZ (BM * LDA) // 4608 floats per buffer
#define BSZ (BK * LDB) // 2176 floats per buffer
#define GEMM_SMEM ((2 * ASZ + 2 * BSZ) * 4)   // 54272 bytes
#define LDC (BN + 4)   // 68 floats, Cs staging

__global__ void __launch_bounds__(256) k_gemm(const float* __restrict__ Aext,
                                              const float* __restrict__ B,
                                              const float* __restrict__ att_s,
                                              const float* __restrict__ att_d,
                                              int M, int K, int layer) {
    const float* __restrict__ A = (layer == 1) ? Aext : (const float*)g_x1;

    extern __shared__ __align__(16) float sm[];
    float* Asb = sm;               // [2][BM][LDA]
    float* Bsb = sm + 2 * ASZ;     // [2][BK][LDB]

    const int tid = threadIdx.x;
    const int wid = tid >> 5;
    const int wm = wid >> 1;      // 0..3
    const int wn = wid & 1;       // 0..1
    const int m0 = blockIdx.y * BM;
    const int n0 = blockIdx.x * BN;

    // per-thread load coords
    const int arow[4] = { (tid + 0) >> 3, (tid + 256) >> 3, (tid + 512) >> 3, (tid + 768) >> 3 };
    const int acol = (tid & 7) * 4;
    const int brow[2] = { (tid + 0) >> 4, (tid + 256) >> 4 };
    const int bcol = (tid & 15) * 4;

    float4 ra[4], rb[2];

    auto loadG = [&](int k0) {
#pragma unroll
        for (int i = 0; i < 4; i++) {
            float4 v = make_float4(0.f, 0.f, 0.f, 0.f);
            if (m0 + arow[i] < M)
                v = *(const float4*)&A[(size_t)(m0 + arow[i]) * K + k0 + acol];
            ra[i] = v;
        }
#pragma unroll
        for (int i = 0; i < 2; i++)
            rb[i] = *(const float4*)&B[(size_t)(k0 + brow[i]) * CHN + n0 + bcol];
    };
    auto storeS = [&](int buf) {
#pragma unroll
        for (int i = 0; i < 4; i++) {
            float* p = &Asb[buf * ASZ + arow[i] * LDA + acol];
            p[0] = wmma::__float_to_tf32(ra[i].x);
            p[1] = wmma::__float_to_tf32(ra[i].y);
            p[2] = wmma::__float_to_tf32(ra[i].z);
            p[3] = wmma::__float_to_tf32(ra[i].w);
        }
#pragma unroll
        for (int i = 0; i < 2; i++) {
            float* p = &Bsb[buf * BSZ + brow[i] * LDB + bcol];
            p[0] = wmma::__float_to_tf32(rb[i].x);
            p[1] = wmma::__float_to_tf32(rb[i].y);
            p[2] = wmma::__float_to_tf32(rb[i].z);
            p[3] = wmma::__float_to_tf32(rb[i].w);
        }
    };

    wmma::fragment<wmma::accumulator, 16, 16, 8, float> c[2][2];
#pragma unroll
    for (int i = 0; i < 2; i++)
#pragma unroll
        for (int j = 0; j < 2; j++) wmma::fill_fragment(c[i][j], 0.f);

    loadG(0);
    storeS(0);
    __syncthreads();

    int buf = 0;
    for (int k0 = 0; k0 < K; k0 += BK) {
        const bool has_next = (k0 + BK) < K;
        if (has_next) loadG(k0 + BK);   // issue LDGs; latency hidden by MMAs

#pragma unroll
        for (int kk = 0; kk < BK; kk += 8) {
            wmma::fragment<wmma::matrix_a, 16, 16, 8, wmma::precision::tf32, wmma::row_major> a[2];
            wmma::fragment<wmma::matrix_b, 16, 16, 8, wmma::precision::tf32, wmma::row_major> b[2];
#pragma unroll
            for (int i = 0; i < 2; i++)
                wmma::load_matrix_sync(a[i], &Asb[buf * ASZ + (wm * 32 + i * 16) * LDA + kk], LDA);
#pragma unroll
            for (int j = 0; j < 2; j++)
                wmma::load_matrix_sync(b[j], &Bsb[buf * BSZ + kk * LDB + wn * 32 + j * 16], LDB);
#pragma unroll
            for (int i = 0; i < 2; i++)
#pragma unroll
                for (int j = 0; j < 2; j++)
                    wmma::mma_sync(c[i][j], a[i], b[j], c[i][j]);
        }

        if (has_next) {
            storeS(buf ^ 1);   // other buffer: no hazard with current reads
            __syncthreads();
            buf ^= 1;
        }
    }

    // global store (g_h padded to NPAD rows, unguarded is safe)
#pragma unroll
    for (int i = 0; i < 2; i++)
#pragma unroll
        for (int j = 0; j < 2; j++)
            wmma::store_matrix_sync(
                &g_h[(size_t)(m0 + wm * 32 + i * 16) * CHN + n0 + wn * 32 + j * 16],
                c[i][j], CHN, wmma::mem_row_major);

    // ---- fused alpha epilogue: stage accumulators into smem, dot per row ----
    __syncthreads();   // done with As/Bs buffers
    float* Cs = sm;    // [BM][LDC] = 128*68 floats = 34816 B (fits in As region)
#pragma unroll
    for (int i = 0; i < 2; i++)
#pragma unroll
        for (int j = 0; j < 2; j++)
            wmma::store_matrix_sync(
                &Cs[(wm * 32 + i * 16) * LDC + wn * 32 + j * 16],
                c[i][j], LDC, wmma::mem_row_major);
    __syncthreads();

    {
        const int r = tid >> 1;           // row 0..127
        const int half = tid & 1;         // channel half
        const int hh = n0 >> 6;           // head for this block
        const float* crow = &Cs[r * LDC + half * 32];
        const float* asp = att_s + n0 + half * 32;
        const float* adp = att_d + n0 + half * 32;
        float s = 0.f, d = 0.f;
#pragma unroll
        for (int cc = 0; cc < 32; cc++) {
            float v = crow[cc];
            s += v * asp[cc];
            d += v * adp[cc];
        }
        s += __shfl_xor_sync(0xffffffffu, s, 1);
        d += __shfl_xor_sync(0xffffffffu, d, 1);
        if (half == 0 && m0 + r < NN) {
            g_as[(m0 + r) * 4 + hh] = s;
            g_ad[(m0 + r) * 4 + hh] = d;
        }
    }
}

// ---------------- per-edge logits, CSR order ---------------------------------
__device__ __forceinline__ float lrelu(float v) { return v > 0.f ? v : 0.2f * v; }

__global__ void k_edge() {
    int p = blockIdx.x * blockDim.x + threadIdx.x;
    if (p >= TT) return;
    int sv = g_srcs[p], dv = g_dsts[p];
    float4 as = *(const float4*)&g_as[sv * 4];
    float4 ad = *(const float4*)&g_ad[dv * 4];
    float4 e;
    e.x = lrelu(as.x + ad.x);
    e.y = lrelu(as.y + ad.y);
    e.z = lrelu(as.z + ad.z);
    e.w = lrelu(as.w + ad.w);
    *(float4*)&g_e[(size_t)p * 4] = e;
}

// ---------------- per-node softmax + aggregation (block per node) -----------
// 4 edge-slots x 64 threads x float4 channels; final 4-way smem reduce.
template <int LAYER>
__global__ void __launch_bounds__(256) k_agg(const float* __restrict__ bias,
                                             float* __restrict__ outext) {
    const int n = blockIdx.x;
    const int tid = threadIdx.x;
    __shared__ float sh_m[4], sh_inv[4];
    __shared__ float s_alpha[64 * 4];
    __shared__ int s_src[64];
    __shared__ __align__(16) float s_red[256 * 4];

    const int row = g_rowptr[n];
    const int deg = g_rowptr[n + 1] - row;
    const int wid = tid >> 5, lane = tid & 31;

    if (wid < 4) {
        float m = -1e30f;
        for (int j = lane; j < deg; j += 32)
            m = fmaxf(m, g_e[(size_t)(row + j) * 4 + wid]);
#pragma unroll
        for (int o = 16; o; o >>= 1) m = fmaxf(m, __shfl_xor_sync(0xffffffffu, m, o));
        float s = 0.f;
        for (int j = lane; j < deg; j += 32)
            s += __expf(g_e[(size_t)(row + j) * 4 + wid] - m);
#pragma unroll
        for (int o = 16; o; o >>= 1) s += __shfl_xor_sync(0xffffffffu, s, o);
        if (lane == 0) { sh_m[wid] = m; sh_inv[wid] = 1.f / (s + 1e-16f); }
    }
    __syncthreads();

    const int grp = tid >> 6;        // edge slot 0..3
    const int ch4 = tid & 63;        // float4 channel group -> channels ch4*4..+3
    const int head = ch4 >> 4;
    float4 acc = make_float4(0.f, 0.f, 0.f, 0.f);

    for (int c0 = 0; c0 < deg; c0 += 64) {
        int cn = min(64, deg - c0);
        if (tid < cn * 4) {
            int j = tid >> 2, hh = tid & 3;
            s_alpha[tid] = __expf(g_e[(size_t)(row + c0 + j) * 4 + hh] - sh_m[hh]) * sh_inv[hh];
        }
        if (tid < cn) s_src[tid] = g_srcs[row + c0 + tid];
        __syncthreads();
        for (int j = grp; j < cn; j += 4) {
            float a = s_alpha[j * 4 + head];
            const float4 hv = *(const float4*)&g_h[(size_t)s_src[j] * CHN + ch4 * 4];
            acc.x += a * hv.x;
            acc.y += a * hv.y;
            acc.z += a * hv.z;
            acc.w += a * hv.w;
        }
        __syncthreads();
    }

    // cross-slot reduce
    *(float4*)&s_red[tid * 4] = acc;
    __syncthreads();
    if (grp == 0) {
        float4 r = acc;
#pragma unroll
        for (int g2 = 1; g2 < 4; g2++) {
            const float4 o = *(const float4*)&s_red[(g2 * 64 + ch4) * 4];
            r.x += o.x; r.y += o.y; r.z += o.z; r.w += o.w;
        }
        const int c = ch4 * 4;
        if (LAYER == 1) {
            const float4 b = *(const float4*)&bias[c];
            float4 o;
            o.x = fmaxf(r.x + b.x, 0.f);
            o.y = fmaxf(r.y + b.y, 0.f);
            o.z = fmaxf(r.z + b.z, 0.f);
            o.w = fmaxf(r.w + b.w, 0.f);
            *(float4*)&g_x1[(size_t)n * CHN + c] = o;
        } else {
            *(float4*)&s_red[c] = r;   // s_red[ch] = total[ch]
        }
    }
    if (LAYER == 2) {
        __syncthreads();
        if (tid < 64)
            outext[(size_t)n * C2 + tid] =
                0.25f * (s_red[tid] + s_red[64 + tid] + s_red[128 + tid] + s_red[192 + tid]) +
                bias[tid];
    }
}

// ---------------- launch -----------------------------------------------------
extern "C" void kernel_launch(void* const* d_in, const int* in_sizes, int n_in,
                              void* d_out, int out_size) {
    const float* x   = (const float*)d_in[0];
    const int*   ei  = (const int*)d_in[1];
    const float* W1  = (const float*)d_in[2];
    const float* as1 = (const float*)d_in[3];
    const float* ad1 = (const float*)d_in[4];
    const float* b1  = (const float*)d_in[5];
    const float* W2  = (const float*)d_in[6];
    const float* as2 = (const float*)d_in[7];
    const float* ad2 = (const float*)d_in[8];
    const float* b2  = (const float*)d_in[9];
    float* out = (float*)d_out;

    cudaFuncSetAttribute(k_gemm, cudaFuncAttributeMaxDynamicSharedMemorySize, GEMM_SMEM);

    // CSR build (shared by both layers)
    k_zero_deg<<<(NN + 255) / 256, 256>>>();
    k_hist<<<(TT + 255) / 256, 256>>>(ei);
    k_scan<<<1, 1024>>>();
    k_scatter<<<(TT + 255) / 256, 256>>>(ei);

    dim3 gemm_grid(CHN / BN, NPAD / BM);

    // ----- layer 1 -----
    k_gemm<<<gemm_grid, 256, GEMM_SMEM>>>(x, W1, as1, ad1, NN, 128, 1);
    k_edge<<<(TT + 255) / 256, 256>>>();
    k_agg<1><<<NN, 256>>>(b1, nullptr);

    // ----- layer 2 -----
    k_gemm<<<gemm_grid, 256, GEMM_SMEM>>>(nullptr, W2, as2, ad2, NN, 256, 2);
    k_edge<<<(TT + 255) / 256, 256>>>();
    k_agg<2><<<NN, 256>>>(b2, out);
}

// round 8
// speedup vs baseline: 1.5040x; 1.3526x over previous
#include <cuda_runtime.h>
#include <mma.h>
using namespace nvcuda;

#define NN 50000
#define NPAD 50048     // NN rounded up to 128 (GEMM tile)
#define EE 800000
#define TT (EE + NN)
#define HH 4
#define CHN 256        // H * C (both layers)
#define C2  64

// ---------------- scratch (device globals; no allocation allowed) ----------
__device__ __align__(16) float g_h[(size_t)NPAD * CHN];   // GEMM output
__device__ __align__(16) float g_x1[(size_t)NPAD * CHN];  // relu(layer1 out)
__device__ __align__(16) float g_as[NN * HH];
__device__ __align__(16) float g_ad[NN * HH];
__device__ __align__(16) float g_e[(size_t)TT * HH];      // CSR-ordered logits
__device__ int   g_deg[NN];
__device__ int   g_rowptr[NN + 1];
__device__ int   g_cursor[NN];
__device__ int   g_srcs[TT];                // CSR (by dst): source node
__device__ int   g_dsts[TT];                // CSR: destination node

// ---------------- CSR build -------------------------------------------------
__global__ void k_zero_deg() {
    int i = blockIdx.x * blockDim.x + threadIdx.x;
    if (i < NN) g_deg[i] = 0;
}

__global__ void k_hist(const int* __restrict__ ei) {
    int t = blockIdx.x * blockDim.x + threadIdx.x;
    if (t >= TT) return;
    int d = (t < EE) ? ei[EE + t] : (t - EE);
    atomicAdd(&g_deg[d], 1);
}

__global__ void k_scan() {
    __shared__ int s[1024];
    const int tid = threadIdx.x;
    const int CHK = (NN + 1023) / 1024;
    int start = tid * CHK;
    int end   = min(start + CHK, NN);
    int sum = 0;
    for (int i = start; i < end; i++) sum += g_deg[i];
    s[tid] = sum;
    __syncthreads();
    for (int off = 1; off < 1024; off <<= 1) {
        int v = (tid >= off) ? s[tid - off] : 0;
        __syncthreads();
        s[tid] += v;
        __syncthreads();
    }
    int run = s[tid] - sum;   // exclusive prefix for this chunk
    for (int i = start; i < end; i++) {
        g_rowptr[i] = run;
        g_cursor[i] = run;
        run += g_deg[i];
    }
    if (tid == 1023) g_rowptr[NN] = s[1023];
}

__global__ void k_scatter(const int* __restrict__ ei) {
    int t = blockIdx.x * blockDim.x + threadIdx.x;
    if (t >= TT) return;
    int sv, dv;
    if (t < EE) { sv = ei[t]; dv = ei[EE + t]; }
    else        { sv = dv = t - EE; }
    int pos = atomicAdd(&g_cursor[dv], 1);
    g_srcs[pos] = sv;
    g_dsts[pos] = dv;
}

// ---------------- tf32 tensor-core GEMM + fused alpha epilogue --------------
#define BM 128
#define BN 64
#define BK 32
#define LDA (BK + 4)   // 36 floats
#define LDB (BN + 4)   // 68 floats
#define ASZ (BM * LDA)
#define BSZ (BK * LDB)
#define GEMM_SMEM ((2 * ASZ + 2 * BSZ) * 4)   // 54272 bytes
#define LDC (BN + 4)

__global__ void __launch_bounds__(256) k_gemm(const float* __restrict__ Aext,
                                              const float* __restrict__ B,
                                              const float* __restrict__ att_s,
                                              const float* __restrict__ att_d,
                                              int M, int K, int layer) {
    const float* __restrict__ A = (layer == 1) ? Aext : (const float*)g_x1;

    extern __shared__ __align__(16) float sm[];
    float* Asb = sm;               // [2][BM][LDA]
    float* Bsb = sm + 2 * ASZ;     // [2][BK][LDB]

    const int tid = threadIdx.x;
    const int wid = tid >> 5;
    const int wm = wid >> 1;
    const int wn = wid & 1;
    const int m0 = blockIdx.y * BM;
    const int n0 = blockIdx.x * BN;

    const int arow[4] = { (tid + 0) >> 3, (tid + 256) >> 3, (tid + 512) >> 3, (tid + 768) >> 3 };
    const int acol = (tid & 7) * 4;
    const int brow[2] = { (tid + 0) >> 4, (tid + 256) >> 4 };
    const int bcol = (tid & 15) * 4;

    float4 ra[4], rb[2];

    auto loadG = [&](int k0) {
#pragma unroll
        for (int i = 0; i < 4; i++) {
            float4 v = make_float4(0.f, 0.f, 0.f, 0.f);
            if (m0 + arow[i] < M)
                v = *(const float4*)&A[(size_t)(m0 + arow[i]) * K + k0 + acol];
            ra[i] = v;
        }
#pragma unroll
        for (int i = 0; i < 2; i++)
            rb[i] = *(const float4*)&B[(size_t)(k0 + brow[i]) * CHN + n0 + bcol];
    };
    auto storeS = [&](int buf) {
#pragma unroll
        for (int i = 0; i < 4; i++) {
            float* p = &Asb[buf * ASZ + arow[i] * LDA + acol];
            p[0] = wmma::__float_to_tf32(ra[i].x);
            p[1] = wmma::__float_to_tf32(ra[i].y);
            p[2] = wmma::__float_to_tf32(ra[i].z);
            p[3] = wmma::__float_to_tf32(ra[i].w);
        }
#pragma unroll
        for (int i = 0; i < 2; i++) {
            float* p = &Bsb[buf * BSZ + brow[i] * LDB + bcol];
            p[0] = wmma::__float_to_tf32(rb[i].x);
            p[1] = wmma::__float_to_tf32(rb[i].y);
            p[2] = wmma::__float_to_tf32(rb[i].z);
            p[3] = wmma::__float_to_tf32(rb[i].w);
        }
    };

    wmma::fragment<wmma::accumulator, 16, 16, 8, float> c[2][2];
#pragma unroll
    for (int i = 0; i < 2; i++)
#pragma unroll
        for (int j = 0; j < 2; j++) wmma::fill_fragment(c[i][j], 0.f);

    loadG(0);
    storeS(0);
    __syncthreads();

    int buf = 0;
    for (int k0 = 0; k0 < K; k0 += BK) {
        const bool has_next = (k0 + BK) < K;
        if (has_next) loadG(k0 + BK);

#pragma unroll
        for (int kk = 0; kk < BK; kk += 8) {
            wmma::fragment<wmma::matrix_a, 16, 16, 8, wmma::precision::tf32, wmma::row_major> a[2];
            wmma::fragment<wmma::matrix_b, 16, 16, 8, wmma::precision::tf32, wmma::row_major> b[2];
#pragma unroll
            for (int i = 0; i < 2; i++)
                wmma::load_matrix_sync(a[i], &Asb[buf * ASZ + (wm * 32 + i * 16) * LDA + kk], LDA);
#pragma unroll
            for (int j = 0; j < 2; j++)
                wmma::load_matrix_sync(b[j], &Bsb[buf * BSZ + kk * LDB + wn * 32 + j * 16], LDB);
#pragma unroll
            for (int i = 0; i < 2; i++)
#pragma unroll
                for (int j = 0; j < 2; j++)
                    wmma::mma_sync(c[i][j], a[i], b[j], c[i][j]);
        }

        if (has_next) {
            storeS(buf ^ 1);
            __syncthreads();
            buf ^= 1;
        }
    }

#pragma unroll
    for (int i = 0; i < 2; i++)
#pragma unroll
        for (int j = 0; j < 2; j++)
            wmma::store_matrix_sync(
                &g_h[(size_t)(m0 + wm * 32 + i * 16) * CHN + n0 + wn * 32 + j * 16],
                c[i][j], CHN, wmma::mem_row_major);

    // ---- fused alpha epilogue ----
    __syncthreads();
    float* Cs = sm;    // [BM][LDC]
#pragma unroll
    for (int i = 0; i < 2; i++)
#pragma unroll
        for (int j = 0; j < 2; j++)
            wmma::store_matrix_sync(
                &Cs[(wm * 32 + i * 16) * LDC + wn * 32 + j * 16],
                c[i][j], LDC, wmma::mem_row_major);
    __syncthreads();

    {
        const int r = tid >> 1;
        const int half = tid & 1;
        const int hh = n0 >> 6;
        const float* crow = &Cs[r * LDC + half * 32];
        const float* asp = att_s + n0 + half * 32;
        const float* adp = att_d + n0 + half * 32;
        float s = 0.f, d = 0.f;
#pragma unroll
        for (int cc = 0; cc < 32; cc++) {
            float v = crow[cc];
            s += v * asp[cc];
            d += v * adp[cc];
        }
        s += __shfl_xor_sync(0xffffffffu, s, 1);
        d += __shfl_xor_sync(0xffffffffu, d, 1);
        if (half == 0 && m0 + r < NN) {
            g_as[(m0 + r) * 4 + hh] = s;
            g_ad[(m0 + r) * 4 + hh] = d;
        }
    }
}

// ---------------- per-edge logits, CSR order ---------------------------------
__device__ __forceinline__ float lrelu(float v) { return v > 0.f ? v : 0.2f * v; }

__global__ void k_edge() {
    int p = blockIdx.x * blockDim.x + threadIdx.x;
    if (p >= TT) return;
    int sv = g_srcs[p], dv = g_dsts[p];
    float4 as = *(const float4*)&g_as[sv * 4];
    float4 ad = *(const float4*)&g_ad[dv * 4];
    float4 e;
    e.x = lrelu(as.x + ad.x);
    e.y = lrelu(as.y + ad.y);
    e.z = lrelu(as.z + ad.z);
    e.w = lrelu(as.w + ad.w);
    *(float4*)&g_e[(size_t)p * 4] = e;
}

// ---------------- warp-per-node softmax + aggregation ------------------------
// Lane owns channels [lane*4, lane*4+4) (heads 0/1) and [128+lane*4, ...) (heads 2/3).
// No shared memory, no barriers.
template <int LAYER>
__global__ void __launch_bounds__(256) k_agg(const float* __restrict__ bias,
                                             float* __restrict__ outext) {
    const int gw = (blockIdx.x * blockDim.x + threadIdx.x) >> 5;
    const int lane = threadIdx.x & 31;
    if (gw >= NN) return;
    const int row = g_rowptr[gw];
    const int deg = g_rowptr[gw + 1] - row;

    // 4-head max
    float4 m4 = make_float4(-1e30f, -1e30f, -1e30f, -1e30f);
    for (int j = lane; j < deg; j += 32) {
        const float4 e = *(const float4*)&g_e[(size_t)(row + j) * 4];
        m4.x = fmaxf(m4.x, e.x);
        m4.y = fmaxf(m4.y, e.y);
        m4.z = fmaxf(m4.z, e.z);
        m4.w = fmaxf(m4.w, e.w);
    }
#pragma unroll
    for (int o = 16; o; o >>= 1) {
        m4.x = fmaxf(m4.x, __shfl_xor_sync(0xffffffffu, m4.x, o));
        m4.y = fmaxf(m4.y, __shfl_xor_sync(0xffffffffu, m4.y, o));
        m4.z = fmaxf(m4.z, __shfl_xor_sync(0xffffffffu, m4.z, o));
        m4.w = fmaxf(m4.w, __shfl_xor_sync(0xffffffffu, m4.w, o));
    }
    // 4-head sum
    float4 s4 = make_float4(0.f, 0.f, 0.f, 0.f);
    for (int j = lane; j < deg; j += 32) {
        const float4 e = *(const float4*)&g_e[(size_t)(row + j) * 4];
        s4.x += __expf(e.x - m4.x);
        s4.y += __expf(e.y - m4.y);
        s4.z += __expf(e.z - m4.z);
        s4.w += __expf(e.w - m4.w);
    }
#pragma unroll
    for (int o = 16; o; o >>= 1) {
        s4.x += __shfl_xor_sync(0xffffffffu, s4.x, o);
        s4.y += __shfl_xor_sync(0xffffffffu, s4.y, o);
        s4.z += __shfl_xor_sync(0xffffffffu, s4.z, o);
        s4.w += __shfl_xor_sync(0xffffffffu, s4.w, o);
    }

    const bool hi = lane >= 16;                 // second head of each pair
    const float mA = hi ? m4.y : m4.x;
    const float mB = hi ? m4.w : m4.z;
    const float iA = 1.f / ((hi ? s4.y : s4.x) + 1e-16f);
    const float iB = 1.f / ((hi ? s4.w : s4.z) + 1e-16f);

    const int cA = lane * 4;                    // first float4 channel base
    float4 accA = make_float4(0.f, 0.f, 0.f, 0.f);
    float4 accB = make_float4(0.f, 0.f, 0.f, 0.f);

#pragma unroll 2
    for (int j = 0; j < deg; j++) {
        const float4 e = *(const float4*)&g_e[(size_t)(row + j) * 4];   // broadcast
        const int src = g_srcs[row + j];                                // broadcast
        const float aA = __expf((hi ? e.y : e.x) - mA) * iA;
        const float aB = __expf((hi ? e.w : e.z) - mB) * iB;
        const float4 h0 = *(const float4*)&g_h[(size_t)src * CHN + cA];
        const float4 h1 = *(const float4*)&g_h[(size_t)src * CHN + 128 + cA];
        accA.x += aA * h0.x; accA.y += aA * h0.y; accA.z += aA * h0.z; accA.w += aA * h0.w;
        accB.x += aB * h1.x; accB.y += aB * h1.y; accB.z += aB * h1.z; accB.w += aB * h1.w;
    }

    if (LAYER == 1) {
        const float4 bA = *(const float4*)&bias[cA];
        const float4 bB = *(const float4*)&bias[128 + cA];
        float4 oA, oB;
        oA.x = fmaxf(accA.x + bA.x, 0.f);
        oA.y = fmaxf(accA.y + bA.y, 0.f);
        oA.z = fmaxf(accA.z + bA.z, 0.f);
        oA.w = fmaxf(accA.w + bA.w, 0.f);
        oB.x = fmaxf(accB.x + bB.x, 0.f);
        oB.y = fmaxf(accB.y + bB.y, 0.f);
        oB.z = fmaxf(accB.z + bB.z, 0.f);
        oB.w = fmaxf(accB.w + bB.w, 0.f);
        *(float4*)&g_x1[(size_t)gw * CHN + cA] = oA;
        *(float4*)&g_x1[(size_t)gw * CHN + 128 + cA] = oB;
    } else {
        // mean over 4 heads: lane L (<16) ends up with channels L*4..L*4+3
        float4 r;
        r.x = accA.x + accB.x;
        r.y = accA.y + accB.y;
        r.z = accA.z + accB.z;
        r.w = accA.w + accB.w;
        r.x += __shfl_xor_sync(0xffffffffu, r.x, 16);
        r.y += __shfl_xor_sync(0xffffffffu, r.y, 16);
        r.z += __shfl_xor_sync(0xffffffffu, r.z, 16);
        r.w += __shfl_xor_sync(0xffffffffu, r.w, 16);
        if (!hi) {
            const float4 b = *(const float4*)&bias[lane * 4];
            float4 o;
            o.x = 0.25f * r.x + b.x;
            o.y = 0.25f * r.y + b.y;
            o.z = 0.25f * r.z + b.z;
            o.w = 0.25f * r.w + b.w;
            *(float4*)&outext[(size_t)gw * C2 + lane * 4] = o;
        }
    }
}

// ---------------- launch -----------------------------------------------------
extern "C" void kernel_launch(void* const* d_in, const int* in_sizes, int n_in,
                              void* d_out, int out_size) {
    const float* x   = (const float*)d_in[0];
    const int*   ei  = (const int*)d_in[1];
    const float* W1  = (const float*)d_in[2];
    const float* as1 = (const float*)d_in[3];
    const float* ad1 = (const float*)d_in[4];
    const float* b1  = (const float*)d_in[5];
    const float* W2  = (const float*)d_in[6];
    const float* as2 = (const float*)d_in[7];
    const float* ad2 = (const float*)d_in[8];
    const float* b2  = (const float*)d_in[9];
    float* out = (float*)d_out;

    cudaFuncSetAttribute(k_gemm, cudaFuncAttributeMaxDynamicSharedMemorySize, GEMM_SMEM);

    // CSR build (shared by both layers)
    k_zero_deg<<<(NN + 255) / 256, 256>>>();
    k_hist<<<(TT + 255) / 256, 256>>>(ei);
    k_scan<<<1, 1024>>>();
    k_scatter<<<(TT + 255) / 256, 256>>>(ei);

    dim3 gemm_grid(CHN / BN, NPAD / BM);
    const int agg_blocks = (NN * 32 + 255) / 256;

    // ----- layer 1 -----
    k_gemm<<<gemm_grid, 256, GEMM_SMEM>>>(x, W1, as1, ad1, NN, 128, 1);
    k_edge<<<(TT + 255) / 256, 256>>>();
    k_agg<1><<<agg_blocks, 256>>>(b1, nullptr);

    // ----- layer 2 -----
    k_gemm<<<gemm_grid, 256, GEMM_SMEM>>>(nullptr, W2, as2, ad2, NN, 256, 2);
    k_edge<<<(TT + 255) / 256, 256>>>();
    k_agg<2><<<agg_blocks, 256>>>(b2, out);
}

// round 9
// speedup vs baseline: 1.5502x; 1.0307x over previous
#include <cuda_runtime.h>
#include <cuda_fp16.h>
#include <mma.h>
using namespace nvcuda;

#define NN 50000
#define NPAD 50048     // NN rounded up to 128 (GEMM tile)
#define EE 800000
#define TT (EE + NN)
#define HH 4
#define CHN 256        // H * C (both layers)
#define C2  64

// ---------------- scratch (device globals; no allocation allowed) ----------
__device__ __align__(16) __half g_h16[(size_t)NPAD * CHN]; // GEMM out (fp16)
__device__ __align__(16) float g_x1[(size_t)NPAD * CHN];   // relu(layer1 out), fp32
__device__ __align__(16) float g_as[NN * HH];
__device__ __align__(16) float g_ad[NN * HH];
__device__ __align__(16) float g_e[(size_t)TT * HH];       // CSR-ordered logits
__device__ int   g_deg[NN];
__device__ int   g_rowptr[NN + 1];
__device__ int   g_cursor[NN];
__device__ int   g_srcs[TT];                // CSR (by dst): source node
__device__ int   g_dsts[TT];                // CSR: destination node

// ---------------- CSR build -------------------------------------------------
__global__ void k_zero_deg() {
    int i = blockIdx.x * blockDim.x + threadIdx.x;
    if (i < NN) g_deg[i] = 0;
}

__global__ void k_hist(const int* __restrict__ ei) {
    int t = blockIdx.x * blockDim.x + threadIdx.x;
    if (t >= TT) return;
    int d = (t < EE) ? ei[EE + t] : (t - EE);
    atomicAdd(&g_deg[d], 1);
}

__global__ void k_scan() {
    __shared__ int s[1024];
    const int tid = threadIdx.x;
    const int CHK = (NN + 1023) / 1024;
    int start = tid * CHK;
    int end   = min(start + CHK, NN);
    int sum = 0;
    for (int i = start; i < end; i++) sum += g_deg[i];
    s[tid] = sum;
    __syncthreads();
    for (int off = 1; off < 1024; off <<= 1) {
        int v = (tid >= off) ? s[tid - off] : 0;
        __syncthreads();
        s[tid] += v;
        __syncthreads();
    }
    int run = s[tid] - sum;   // exclusive prefix for this chunk
    for (int i = start; i < end; i++) {
        g_rowptr[i] = run;
        g_cursor[i] = run;
        run += g_deg[i];
    }
    if (tid == 1023) g_rowptr[NN] = s[1023];
}

__global__ void k_scatter(const int* __restrict__ ei) {
    int t = blockIdx.x * blockDim.x + threadIdx.x;
    if (t >= TT) return;
    int sv, dv;
    if (t < EE) { sv = ei[t]; dv = ei[EE + t]; }
    else        { sv = dv = t - EE; }
    int pos = atomicAdd(&g_cursor[dv], 1);
    g_srcs[pos] = sv;
    g_dsts[pos] = dv;
}

// ---------------- tf32 tensor-core GEMM + fused alpha/fp16 epilogue ---------
#define BM 128
#define BN 64
#define BK 32
#define LDA (BK + 4)   // 36 floats
#define LDB (BN + 4)   // 68 floats
#define ASZ (BM * LDA)
#define BSZ (BK * LDB)
#define GEMM_SMEM ((2 * ASZ + 2 * BSZ) * 4)   // 54272 bytes
#define LDC (BN + 4)

__global__ void __launch_bounds__(256) k_gemm(const float* __restrict__ Aext,
                                              const float* __restrict__ B,
                                              const float* __restrict__ att_s,
                                              const float* __restrict__ att_d,
                                              int M, int K, int layer) {
    const float* __restrict__ A = (layer == 1) ? Aext : (const float*)g_x1;

    extern __shared__ __align__(16) float sm[];
    float* Asb = sm;               // [2][BM][LDA]
    float* Bsb = sm + 2 * ASZ;     // [2][BK][LDB]

    const int tid = threadIdx.x;
    const int wid = tid >> 5;
    const int wm = wid >> 1;
    const int wn = wid & 1;
    const int m0 = blockIdx.y * BM;
    const int n0 = blockIdx.x * BN;

    const int arow[4] = { (tid + 0) >> 3, (tid + 256) >> 3, (tid + 512) >> 3, (tid + 768) >> 3 };
    const int acol = (tid & 7) * 4;
    const int brow[2] = { (tid + 0) >> 4, (tid + 256) >> 4 };
    const int bcol = (tid & 15) * 4;

    float4 ra[4], rb[2];

    auto loadG = [&](int k0) {
#pragma unroll
        for (int i = 0; i < 4; i++) {
            float4 v = make_float4(0.f, 0.f, 0.f, 0.f);
            if (m0 + arow[i] < M)
                v = *(const float4*)&A[(size_t)(m0 + arow[i]) * K + k0 + acol];
            ra[i] = v;
        }
#pragma unroll
        for (int i = 0; i < 2; i++)
            rb[i] = *(const float4*)&B[(size_t)(k0 + brow[i]) * CHN + n0 + bcol];
    };
    auto storeS = [&](int buf) {
#pragma unroll
        for (int i = 0; i < 4; i++) {
            float* p = &Asb[buf * ASZ + arow[i] * LDA + acol];
            p[0] = wmma::__float_to_tf32(ra[i].x);
            p[1] = wmma::__float_to_tf32(ra[i].y);
            p[2] = wmma::__float_to_tf32(ra[i].z);
            p[3] = wmma::__float_to_tf32(ra[i].w);
        }
#pragma unroll
        for (int i = 0; i < 2; i++) {
            float* p = &Bsb[buf * BSZ + brow[i] * LDB + bcol];
            p[0] = wmma::__float_to_tf32(rb[i].x);
            p[1] = wmma::__float_to_tf32(rb[i].y);
            p[2] = wmma::__float_to_tf32(rb[i].z);
            p[3] = wmma::__float_to_tf32(rb[i].w);
        }
    };

    wmma::fragment<wmma::accumulator, 16, 16, 8, float> c[2][2];
#pragma unroll
    for (int i = 0; i < 2; i++)
#pragma unroll
        for (int j = 0; j < 2; j++) wmma::fill_fragment(c[i][j], 0.f);

    loadG(0);
    storeS(0);
    __syncthreads();

    int buf = 0;
    for (int k0 = 0; k0 < K; k0 += BK) {
        const bool has_next = (k0 + BK) < K;
        if (has_next) loadG(k0 + BK);

#pragma unroll
        for (int kk = 0; kk < BK; kk += 8) {
            wmma::fragment<wmma::matrix_a, 16, 16, 8, wmma::precision::tf32, wmma::row_major> a[2];
            wmma::fragment<wmma::matrix_b, 16, 16, 8, wmma::precision::tf32, wmma::row_major> b[2];
#pragma unroll
            for (int i = 0; i < 2; i++)
                wmma::load_matrix_sync(a[i], &Asb[buf * ASZ + (wm * 32 + i * 16) * LDA + kk], LDA);
#pragma unroll
            for (int j = 0; j < 2; j++)
                wmma::load_matrix_sync(b[j], &Bsb[buf * BSZ + kk * LDB + wn * 32 + j * 16], LDB);
#pragma unroll
            for (int i = 0; i < 2; i++)
#pragma unroll
                for (int j = 0; j < 2; j++)
                    wmma::mma_sync(c[i][j], a[i], b[j], c[i][j]);
        }

        if (has_next) {
            storeS(buf ^ 1);
            __syncthreads();
            buf ^= 1;
        }
    }

    // ---- epilogue: stage accumulators into smem once ----
    __syncthreads();
    float* Cs = sm;    // [BM][LDC]
#pragma unroll
    for (int i = 0; i < 2; i++)
#pragma unroll
        for (int j = 0; j < 2; j++)
            wmma::store_matrix_sync(
                &Cs[(wm * 32 + i * 16) * LDC + wn * 32 + j * 16],
                c[i][j], LDC, wmma::mem_row_major);
    __syncthreads();

    {
        const int r = tid >> 1;           // row 0..127
        const int half = tid & 1;         // col half
        const float* crow = &Cs[r * LDC + half * 32];

        // (a) fp16 store of the 32 output channels
        uint4 w[4];
        __half2* wh = (__half2*)w;
#pragma unroll
        for (int i = 0; i < 16; i++)
            wh[i] = __floats2half2_rn(crow[2 * i], crow[2 * i + 1]);
        uint4* dst = (uint4*)&g_h16[(size_t)(m0 + r) * CHN + n0 + half * 32];
#pragma unroll
        for (int i = 0; i < 4; i++) dst[i] = w[i];

        // (b) fused alpha dot products
        const int hh = n0 >> 6;
        const float* asp = att_s + n0 + half * 32;
        const float* adp = att_d + n0 + half * 32;
        float s = 0.f, d = 0.f;
#pragma unroll
        for (int cc = 0; cc < 32; cc++) {
            float v = crow[cc];
            s += v * asp[cc];
            d += v * adp[cc];
        }
        s += __shfl_xor_sync(0xffffffffu, s, 1);
        d += __shfl_xor_sync(0xffffffffu, d, 1);
        if (half == 0 && m0 + r < NN) {
            g_as[(m0 + r) * 4 + hh] = s;
            g_ad[(m0 + r) * 4 + hh] = d;
        }
    }
}

// ---------------- per-edge logits, CSR order ---------------------------------
__device__ __forceinline__ float lrelu(float v) { return v > 0.f ? v : 0.2f * v; }

__global__ void k_edge() {
    int p = blockIdx.x * blockDim.x + threadIdx.x;
    if (p >= TT) return;
    int sv = g_srcs[p], dv = g_dsts[p];
    float4 as = *(const float4*)&g_as[sv * 4];
    float4 ad = *(const float4*)&g_ad[dv * 4];
    float4 e;
    e.x = lrelu(as.x + ad.x);
    e.y = lrelu(as.y + ad.y);
    e.z = lrelu(as.z + ad.z);
    e.w = lrelu(as.w + ad.w);
    *(float4*)&g_e[(size_t)p * 4] = e;
}

// ---------------- warp-per-node softmax + aggregation (fp16 gather) ---------
template <int LAYER>
__global__ void __launch_bounds__(256) k_agg(const float* __restrict__ bias,
                                             float* __restrict__ outext) {
    const int gw = (blockIdx.x * blockDim.x + threadIdx.x) >> 5;
    const int lane = threadIdx.x & 31;
    if (gw >= NN) return;
    const int row = g_rowptr[gw];
    const int deg = g_rowptr[gw + 1] - row;

    // 4-head max
    float4 m4 = make_float4(-1e30f, -1e30f, -1e30f, -1e30f);
    for (int j = lane; j < deg; j += 32) {
        const float4 e = *(const float4*)&g_e[(size_t)(row + j) * 4];
        m4.x = fmaxf(m4.x, e.x);
        m4.y = fmaxf(m4.y, e.y);
        m4.z = fmaxf(m4.z, e.z);
        m4.w = fmaxf(m4.w, e.w);
    }
#pragma unroll
    for (int o = 16; o; o >>= 1) {
        m4.x = fmaxf(m4.x, __shfl_xor_sync(0xffffffffu, m4.x, o));
        m4.y = fmaxf(m4.y, __shfl_xor_sync(0xffffffffu, m4.y, o));
        m4.z = fmaxf(m4.z, __shfl_xor_sync(0xffffffffu, m4.z, o));
        m4.w = fmaxf(m4.w, __shfl_xor_sync(0xffffffffu, m4.w, o));
    }
    // 4-head sum
    float4 s4 = make_float4(0.f, 0.f, 0.f, 0.f);
    for (int j = lane; j < deg; j += 32) {
        const float4 e = *(const float4*)&g_e[(size_t)(row + j) * 4];
        s4.x += __expf(e.x - m4.x);
        s4.y += __expf(e.y - m4.y);
        s4.z += __expf(e.z - m4.z);
        s4.w += __expf(e.w - m4.w);
    }
#pragma unroll
    for (int o = 16; o; o >>= 1) {
        s4.x += __shfl_xor_sync(0xffffffffu, s4.x, o);
        s4.y += __shfl_xor_sync(0xffffffffu, s4.y, o);
        s4.z += __shfl_xor_sync(0xffffffffu, s4.z, o);
        s4.w += __shfl_xor_sync(0xffffffffu, s4.w, o);
    }

    const bool hi = lane >= 16;
    const float mA = hi ? m4.y : m4.x;
    const float mB = hi ? m4.w : m4.z;
    const float iA = 1.f / ((hi ? s4.y : s4.x) + 1e-16f);
    const float iB = 1.f / ((hi ? s4.w : s4.z) + 1e-16f);

    const int cA = lane * 4;
    float4 accA = make_float4(0.f, 0.f, 0.f, 0.f);
    float4 accB = make_float4(0.f, 0.f, 0.f, 0.f);

#pragma unroll 2
    for (int j = 0; j < deg; j++) {
        const float4 e = *(const float4*)&g_e[(size_t)(row + j) * 4];   // broadcast
        const int src = g_srcs[row + j];                                // broadcast
        const float aA = __expf((hi ? e.y : e.x) - mA) * iA;
        const float aB = __expf((hi ? e.w : e.z) - mB) * iB;
        const uint2 u0 = *(const uint2*)(g_h16 + (size_t)src * CHN + cA);
        const uint2 u1 = *(const uint2*)(g_h16 + (size_t)src * CHN + 128 + cA);
        const float2 f00 = __half22float2(*(const __half2*)&u0.x);
        const float2 f01 = __half22float2(*(const __half2*)&u0.y);
        const float2 f10 = __half22float2(*(const __half2*)&u1.x);
        const float2 f11 = __half22float2(*(const __half2*)&u1.y);
        accA.x += aA * f00.x; accA.y += aA * f00.y;
        accA.z += aA * f01.x; accA.w += aA * f01.y;
        accB.x += aB * f10.x; accB.y += aB * f10.y;
        accB.z += aB * f11.x; accB.w += aB * f11.y;
    }

    if (LAYER == 1) {
        const float4 bA = *(const float4*)&bias[cA];
        const float4 bB = *(const float4*)&bias[128 + cA];
        float4 oA, oB;
        oA.x = fmaxf(accA.x + bA.x, 0.f);
        oA.y = fmaxf(accA.y + bA.y, 0.f);
        oA.z = fmaxf(accA.z + bA.z, 0.f);
        oA.w = fmaxf(accA.w + bA.w, 0.f);
        oB.x = fmaxf(accB.x + bB.x, 0.f);
        oB.y = fmaxf(accB.y + bB.y, 0.f);
        oB.z = fmaxf(accB.z + bB.z, 0.f);
        oB.w = fmaxf(accB.w + bB.w, 0.f);
        *(float4*)&g_x1[(size_t)gw * CHN + cA] = oA;
        *(float4*)&g_x1[(size_t)gw * CHN + 128 + cA] = oB;
    } else {
        float4 r;
        r.x = accA.x + accB.x;
        r.y = accA.y + accB.y;
        r.z = accA.z + accB.z;
        r.w = accA.w + accB.w;
        r.x += __shfl_xor_sync(0xffffffffu, r.x, 16);
        r.y += __shfl_xor_sync(0xffffffffu, r.y, 16);
        r.z += __shfl_xor_sync(0xffffffffu, r.z, 16);
        r.w += __shfl_xor_sync(0xffffffffu, r.w, 16);
        if (!hi) {
            const float4 b = *(const float4*)&bias[lane * 4];
            float4 o;
            o.x = 0.25f * r.x + b.x;
            o.y = 0.25f * r.y + b.y;
            o.z = 0.25f * r.z + b.z;
            o.w = 0.25f * r.w + b.w;
            *(float4*)&outext[(size_t)gw * C2 + lane * 4] = o;
        }
    }
}

// ---------------- launch -----------------------------------------------------
extern "C" void kernel_launch(void* const* d_in, const int* in_sizes, int n_in,
                              void* d_out, int out_size) {
    const float* x   = (const float*)d_in[0];
    const int*   ei  = (const int*)d_in[1];
    const float* W1  = (const float*)d_in[2];
    const float* as1 = (const float*)d_in[3];
    const float* ad1 = (const float*)d_in[4];
    const float* b1  = (const float*)d_in[5];
    const float* W2  = (const float*)d_in[6];
    const float* as2 = (const float*)d_in[7];
    const float* ad2 = (const float*)d_in[8];
    const float* b2  = (const float*)d_in[9];
    float* out = (float*)d_out;

    cudaFuncSetAttribute(k_gemm, cudaFuncAttributeMaxDynamicSharedMemorySize, GEMM_SMEM);

    // CSR build (shared by both layers)
    k_zero_deg<<<(NN + 255) / 256, 256>>>();
    k_hist<<<(TT + 255) / 256, 256>>>(ei);
    k_scan<<<1, 1024>>>();
    k_scatter<<<(TT + 255) / 256, 256>>>(ei);

    dim3 gemm_grid(CHN / BN, NPAD / BM);
    const int agg_blocks = (NN * 32 + 255) / 256;

    // ----- layer 1 -----
    k_gemm<<<gemm_grid, 256, GEMM_SMEM>>>(x, W1, as1, ad1, NN, 128, 1);
    k_edge<<<(TT + 255) / 256, 256>>>();
    k_agg<1><<<agg_blocks, 256>>>(b1, nullptr);

    // ----- layer 2 -----
    k_gemm<<<gemm_grid, 256, GEMM_SMEM>>>(nullptr, W2, as2, ad2, NN, 256, 2);
    k_edge<<<(TT + 255) / 256, 256>>>();
    k_agg<2><<<agg_blocks, 256>>>(b2, out);
}

// round 10
// speedup vs baseline: 2.1085x; 1.3602x over previous
#include <cuda_runtime.h>
#include <cuda_fp16.h>
#include <mma.h>
using namespace nvcuda;

#define NN 50000
#define NPAD 50048     // NN rounded up to 128 (GEMM tile)
#define EE 800000
#define TT (EE + NN)
#define HH 4
#define CHN 256        // H * C (both layers)
#define C2  64

// ---------------- scratch (device globals; no allocation allowed) ----------
__device__ __align__(16) __half g_h16[(size_t)NPAD * CHN];  // GEMM out (fp16)
__device__ __align__(16) __half g_x1h[(size_t)NPAD * CHN];  // relu(layer1 out), fp16
__device__ __align__(16) float g_as[NN * HH];
__device__ __align__(16) float g_ad[NN * HH];
__device__ __align__(16) float g_e[(size_t)TT * HH];        // CSR-ordered logits
__device__ int   g_deg[NN];
__device__ int   g_rowptr[NN + 1];
__device__ int   g_cursor[NN];
__device__ int   g_srcs[TT];
__device__ int   g_dsts[TT];

// ---------------- CSR build -------------------------------------------------
__global__ void k_zero_deg() {
    int i = blockIdx.x * blockDim.x + threadIdx.x;
    if (i < NN) g_deg[i] = 0;
}

__global__ void k_hist(const int* __restrict__ ei) {
    int t = blockIdx.x * blockDim.x + threadIdx.x;
    if (t >= TT) return;
    int d = (t < EE) ? ei[EE + t] : (t - EE);
    atomicAdd(&g_deg[d], 1);
}

__global__ void k_scan() {
    __shared__ int s[1024];
    const int tid = threadIdx.x;
    const int CHK = (NN + 1023) / 1024;
    int start = tid * CHK;
    int end   = min(start + CHK, NN);
    int sum = 0;
    for (int i = start; i < end; i++) sum += g_deg[i];
    s[tid] = sum;
    __syncthreads();
    for (int off = 1; off < 1024; off <<= 1) {
        int v = (tid >= off) ? s[tid - off] : 0;
        __syncthreads();
        s[tid] += v;
        __syncthreads();
    }
    int run = s[tid] - sum;
    for (int i = start; i < end; i++) {
        g_rowptr[i] = run;
        g_cursor[i] = run;
        run += g_deg[i];
    }
    if (tid == 1023) g_rowptr[NN] = s[1023];
}

__global__ void k_scatter(const int* __restrict__ ei) {
    int t = blockIdx.x * blockDim.x + threadIdx.x;
    if (t >= TT) return;
    int sv, dv;
    if (t < EE) { sv = ei[t]; dv = ei[EE + t]; }
    else        { sv = dv = t - EE; }
    int pos = atomicAdd(&g_cursor[dv], 1);
    g_srcs[pos] = sv;
    g_dsts[pos] = dv;
}

// ---------------- fp16 tensor-core GEMM + fused alpha/fp16 epilogue ---------
// C[M,256] = A[M,K] @ B[K,256]. BM=128, BN=64, BK=32; double-buffered static
// smem (fp16 tiles); 8 warps 4x2; warp tile 32x32 via 2x2 m16n16k16 frags.
#define BM 128
#define BN 64
#define BK 32
#define LDAH (BK + 8)   // 40 halfs (80B rows, 16B mult)
#define LDBH (BN + 8)   // 72 halfs (144B rows)
#define ASZH (BM * LDAH)   // per buffer, halfs
#define BSZH (BK * LDBH)
#define LDC (BN + 4)
// smem byte budget: tiles 2*(ASZH+BSZH)*2 = 29696; Cs staging 128*68*4 = 34816
#define SMEM_BYTES 34816

template <int LAYER>
__global__ void __launch_bounds__(256) k_gemm(const float* __restrict__ Aext,
                                              const float* __restrict__ B,
                                              const float* __restrict__ att_s,
                                              const float* __restrict__ att_d,
                                              int M, int K) {
    __shared__ __align__(16) char smbuf[SMEM_BYTES];
    __half* Ash = (__half*)smbuf;                     // [2][BM][LDAH]
    __half* Bsh = (__half*)(smbuf + 2 * ASZH * 2);    // [2][BK][LDBH]

    const int tid = threadIdx.x;
    const int wid = tid >> 5;
    const int wm = wid >> 1;
    const int wn = wid & 1;
    const int m0 = blockIdx.y * BM;
    const int n0 = blockIdx.x * BN;

    // B tile: 32x64 floats = 512 float4 -> 2 per thread
    const int brow[2] = { (tid + 0) >> 4, (tid + 256) >> 4 };
    const int bcol = (tid & 15) * 4;
    float4 rbf[2];

    // A tile coords
    // fp32 path: 128x32 floats = 1024 float4 -> 4 per thread
    const int arow_f[4] = { (tid + 0) >> 3, (tid + 256) >> 3, (tid + 512) >> 3, (tid + 768) >> 3 };
    const int acol_f = (tid & 7) * 4;
    float4 raf[4];
    // fp16 path: 128x32 halfs = 512 uint4 -> 2 per thread
    const int arow_h[2] = { (tid + 0) >> 2, (tid + 256) >> 2 };
    const int acol_h = (tid & 3) * 8;
    uint4 rah[2];

    auto loadG = [&](int k0) {
        if (LAYER == 1) {
#pragma unroll
            for (int i = 0; i < 4; i++) {
                float4 v = make_float4(0.f, 0.f, 0.f, 0.f);
                if (m0 + arow_f[i] < M)
                    v = *(const float4*)&Aext[(size_t)(m0 + arow_f[i]) * K + k0 + acol_f];
                raf[i] = v;
            }
        } else {
#pragma unroll
            for (int i = 0; i < 2; i++)
                rah[i] = *(const uint4*)&g_x1h[(size_t)(m0 + arow_h[i]) * K + k0 + acol_h];
        }
#pragma unroll
        for (int i = 0; i < 2; i++)
            rbf[i] = *(const float4*)&B[(size_t)(k0 + brow[i]) * CHN + n0 + bcol];
    };
    auto storeS = [&](int buf) {
        if (LAYER == 1) {
#pragma unroll
            for (int i = 0; i < 4; i++) {
                __half2* p = (__half2*)&Ash[buf * ASZH + arow_f[i] * LDAH + acol_f];
                p[0] = __floats2half2_rn(raf[i].x, raf[i].y);
                p[1] = __floats2half2_rn(raf[i].z, raf[i].w);
            }
        } else {
#pragma unroll
            for (int i = 0; i < 2; i++)
                *(uint4*)&Ash[buf * ASZH + arow_h[i] * LDAH + acol_h] = rah[i];
        }
#pragma unroll
        for (int i = 0; i < 2; i++) {
            __half2* p = (__half2*)&Bsh[buf * BSZH + brow[i] * LDBH + bcol];
            p[0] = __floats2half2_rn(rbf[i].x, rbf[i].y);
            p[1] = __floats2half2_rn(rbf[i].z, rbf[i].w);
        }
    };

    wmma::fragment<wmma::accumulator, 16, 16, 16, float> c[2][2];
#pragma unroll
    for (int i = 0; i < 2; i++)
#pragma unroll
        for (int j = 0; j < 2; j++) wmma::fill_fragment(c[i][j], 0.f);

    loadG(0);
    storeS(0);
    __syncthreads();

    int buf = 0;
    for (int k0 = 0; k0 < K; k0 += BK) {
        const bool has_next = (k0 + BK) < K;
        if (has_next) loadG(k0 + BK);

#pragma unroll
        for (int kk = 0; kk < BK; kk += 16) {
            wmma::fragment<wmma::matrix_a, 16, 16, 16, __half, wmma::row_major> a[2];
            wmma::fragment<wmma::matrix_b, 16, 16, 16, __half, wmma::row_major> b[2];
#pragma unroll
            for (int i = 0; i < 2; i++)
                wmma::load_matrix_sync(a[i], &Ash[buf * ASZH + (wm * 32 + i * 16) * LDAH + kk], LDAH);
#pragma unroll
            for (int j = 0; j < 2; j++)
                wmma::load_matrix_sync(b[j], &Bsh[buf * BSZH + kk * LDBH + wn * 32 + j * 16], LDBH);
#pragma unroll
            for (int i = 0; i < 2; i++)
#pragma unroll
                for (int j = 0; j < 2; j++)
                    wmma::mma_sync(c[i][j], a[i], b[j], c[i][j]);
        }

        if (has_next) {
            storeS(buf ^ 1);
            __syncthreads();
            buf ^= 1;
        }
    }

    // ---- epilogue: stage accumulators into smem once ----
    __syncthreads();
    float* Cs = (float*)smbuf;   // [BM][LDC]
#pragma unroll
    for (int i = 0; i < 2; i++)
#pragma unroll
        for (int j = 0; j < 2; j++)
            wmma::store_matrix_sync(
                &Cs[(wm * 32 + i * 16) * LDC + wn * 32 + j * 16],
                c[i][j], LDC, wmma::mem_row_major);
    __syncthreads();

    {
        const int r = tid >> 1;           // row 0..127
        const int half = tid & 1;         // col half
        const float* crow = &Cs[r * LDC + half * 32];

        // (a) fp16 store of the 32 output channels
        uint4 w[4];
        __half2* wh = (__half2*)w;
#pragma unroll
        for (int i = 0; i < 16; i++)
            wh[i] = __floats2half2_rn(crow[2 * i], crow[2 * i + 1]);
        uint4* dst = (uint4*)&g_h16[(size_t)(m0 + r) * CHN + n0 + half * 32];
#pragma unroll
        for (int i = 0; i < 4; i++) dst[i] = w[i];

        // (b) fused alpha dot products
        const int hh = n0 >> 6;
        const float* asp = att_s + n0 + half * 32;
        const float* adp = att_d + n0 + half * 32;
        float s = 0.f, d = 0.f;
#pragma unroll
        for (int cc = 0; cc < 32; cc++) {
            float v = crow[cc];
            s += v * asp[cc];
            d += v * adp[cc];
        }
        s += __shfl_xor_sync(0xffffffffu, s, 1);
        d += __shfl_xor_sync(0xffffffffu, d, 1);
        if (half == 0 && m0 + r < NN) {
            g_as[(m0 + r) * 4 + hh] = s;
            g_ad[(m0 + r) * 4 + hh] = d;
        }
    }
}

// ---------------- per-edge logits, CSR order ---------------------------------
__device__ __forceinline__ float lrelu(float v) { return v > 0.f ? v : 0.2f * v; }

__global__ void k_edge() {
    int p = blockIdx.x * blockDim.x + threadIdx.x;
    if (p >= TT) return;
    int sv = g_srcs[p], dv = g_dsts[p];
    float4 as = *(const float4*)&g_as[sv * 4];
    float4 ad = *(const float4*)&g_ad[dv * 4];
    float4 e;
    e.x = lrelu(as.x + ad.x);
    e.y = lrelu(as.y + ad.y);
    e.z = lrelu(as.z + ad.z);
    e.w = lrelu(as.w + ad.w);
    *(float4*)&g_e[(size_t)p * 4] = e;
}

// ---------------- warp-per-node softmax + aggregation (fp16 gather) ---------
template <int LAYER>
__global__ void __launch_bounds__(256) k_agg(const float* __restrict__ bias,
                                             float* __restrict__ outext) {
    const int gw = (blockIdx.x * blockDim.x + threadIdx.x) >> 5;
    const int lane = threadIdx.x & 31;
    if (gw >= NN) return;
    const int row = g_rowptr[gw];
    const int deg = g_rowptr[gw + 1] - row;

    // 4-head max
    float4 m4 = make_float4(-1e30f, -1e30f, -1e30f, -1e30f);
    for (int j = lane; j < deg; j += 32) {
        const float4 e = *(const float4*)&g_e[(size_t)(row + j) * 4];
        m4.x = fmaxf(m4.x, e.x);
        m4.y = fmaxf(m4.y, e.y);
        m4.z = fmaxf(m4.z, e.z);
        m4.w = fmaxf(m4.w, e.w);
    }
#pragma unroll
    for (int o = 16; o; o >>= 1) {
        m4.x = fmaxf(m4.x, __shfl_xor_sync(0xffffffffu, m4.x, o));
        m4.y = fmaxf(m4.y, __shfl_xor_sync(0xffffffffu, m4.y, o));
        m4.z = fmaxf(m4.z, __shfl_xor_sync(0xffffffffu, m4.z, o));
        m4.w = fmaxf(m4.w, __shfl_xor_sync(0xffffffffu, m4.w, o));
    }
    // 4-head sum
    float4 s4 = make_float4(0.f, 0.f, 0.f, 0.f);
    for (int j = lane; j < deg; j += 32) {
        const float4 e = *(const float4*)&g_e[(size_t)(row + j) * 4];
        s4.x += __expf(e.x - m4.x);
        s4.y += __expf(e.y - m4.y);
        s4.z += __expf(e.z - m4.z);
        s4.w += __expf(e.w - m4.w);
    }
#pragma unroll
    for (int o = 16; o; o >>= 1) {
        s4.x += __shfl_xor_sync(0xffffffffu, s4.x, o);
        s4.y += __shfl_xor_sync(0xffffffffu, s4.y, o);
        s4.z += __shfl_xor_sync(0xffffffffu, s4.z, o);
        s4.w += __shfl_xor_sync(0xffffffffu, s4.w, o);
    }

    const bool hi = lane >= 16;
    const float mA = hi ? m4.y : m4.x;
    const float mB = hi ? m4.w : m4.z;
    const float iA = 1.f / ((hi ? s4.y : s4.x) + 1e-16f);
    const float iB = 1.f / ((hi ? s4.w : s4.z) + 1e-16f);

    const int cA = lane * 4;
    float4 accA = make_float4(0.f, 0.f, 0.f, 0.f);
    float4 accB = make_float4(0.f, 0.f, 0.f, 0.f);

#pragma unroll 2
    for (int j = 0; j < deg; j++) {
        const float4 e = *(const float4*)&g_e[(size_t)(row + j) * 4];   // broadcast
        const int src = g_srcs[row + j];                                // broadcast
        const float aA = __expf((hi ? e.y : e.x) - mA) * iA;
        const float aB = __expf((hi ? e.w : e.z) - mB) * iB;
        const uint2 u0 = *(const uint2*)(g_h16 + (size_t)src * CHN + cA);
        const uint2 u1 = *(const uint2*)(g_h16 + (size_t)src * CHN + 128 + cA);
        const float2 f00 = __half22float2(*(const __half2*)&u0.x);
        const float2 f01 = __half22float2(*(const __half2*)&u0.y);
        const float2 f10 = __half22float2(*(const __half2*)&u1.x);
        const float2 f11 = __half22float2(*(const __half2*)&u1.y);
        accA.x += aA * f00.x; accA.y += aA * f00.y;
        accA.z += aA * f01.x; accA.w += aA * f01.y;
        accB.x += aB * f10.x; accB.y += aB * f10.y;
        accB.z += aB * f11.x; accB.w += aB * f11.y;
    }

    if (LAYER == 1) {
        const float4 bA = *(const float4*)&bias[cA];
        const float4 bB = *(const float4*)&bias[128 + cA];
        uint2 oA, oB;
        ((__half2*)&oA)[0] = __floats2half2_rn(fmaxf(accA.x + bA.x, 0.f), fmaxf(accA.y + bA.y, 0.f));
        ((__half2*)&oA)[1] = __floats2half2_rn(fmaxf(accA.z + bA.z, 0.f), fmaxf(accA.w + bA.w, 0.f));
        ((__half2*)&oB)[0] = __floats2half2_rn(fmaxf(accB.x + bB.x, 0.f), fmaxf(accB.y + bB.y, 0.f));
        ((__half2*)&oB)[1] = __floats2half2_rn(fmaxf(accB.z + bB.z, 0.f), fmaxf(accB.w + bB.w, 0.f));
        *(uint2*)&g_x1h[(size_t)gw * CHN + cA] = oA;
        *(uint2*)&g_x1h[(size_t)gw * CHN + 128 + cA] = oB;
    } else {
        float4 r;
        r.x = accA.x + accB.x;
        r.y = accA.y + accB.y;
        r.z = accA.z + accB.z;
        r.w = accA.w + accB.w;
        r.x += __shfl_xor_sync(0xffffffffu, r.x, 16);
        r.y += __shfl_xor_sync(0xffffffffu, r.y, 16);
        r.z += __shfl_xor_sync(0xffffffffu, r.z, 16);
        r.w += __shfl_xor_sync(0xffffffffu, r.w, 16);
        if (!hi) {
            const float4 b = *(const float4*)&bias[lane * 4];
            float4 o;
            o.x = 0.25f * r.x + b.x;
            o.y = 0.25f * r.y + b.y;
            o.z = 0.25f * r.z + b.z;
            o.w = 0.25f * r.w + b.w;
            *(float4*)&outext[(size_t)gw * C2 + lane * 4] = o;
        }
    }
}

// ---------------- launch -----------------------------------------------------
extern "C" void kernel_launch(void* const* d_in, const int* in_sizes, int n_in,
                              void* d_out, int out_size) {
    const float* x   = (const float*)d_in[0];
    const int*   ei  = (const int*)d_in[1];
    const float* W1  = (const float*)d_in[2];
    const float* as1 = (const float*)d_in[3];
    const float* ad1 = (const float*)d_in[4];
    const float* b1  = (const float*)d_in[5];
    const float* W2  = (const float*)d_in[6];
    const float* as2 = (const float*)d_in[7];
    const float* ad2 = (const float*)d_in[8];
    const float* b2  = (const float*)d_in[9];
    float* out = (float*)d_out;

    // CSR build (shared by both layers)
    k_zero_deg<<<(NN + 255) / 256, 256>>>();
    k_hist<<<(TT + 255) / 256, 256>>>(ei);
    k_scan<<<1, 1024>>>();
    k_scatter<<<(TT + 255) / 256, 256>>>(ei);

    dim3 gemm_grid(CHN / BN, NPAD / BM);
    const int agg_blocks = (NN * 32 + 255) / 256;

    // ----- layer 1 -----
    k_gemm<1><<<gemm_grid, 256>>>(x, W1, as1, ad1, NN, 128);
    k_edge<<<(TT + 255) / 256, 256>>>();
    k_agg<1><<<agg_blocks, 256>>>(b1, nullptr);

    // ----- layer 2 -----
    k_gemm<2><<<gemm_grid, 256>>>(nullptr, W2, as2, ad2, NN, 256);
    k_edge<<<(TT + 255) / 256, 256>>>();
    k_agg<2><<<agg_blocks, 256>>>(b2, out);
}